// round 1
// baseline (speedup 1.0000x reference)
#include <cuda_runtime.h>

// Problem constants
#define BB   256
#define TT   100
#define NG   2048
#define NP   512
#define G4   8192          // 4*NG
#define MTR  (BB * TT)     // 25600 rows for dense/dec stages

// ---------------------------------------------------------------------------
// Static device scratch (no allocations allowed in kernel_launch)
// ---------------------------------------------------------------------------
__device__ float d_W2pk[2 * G4];                  // collapsed v->gates weights, gate-interleaved
__device__ float d_b2pk[G4];                      // collapsed bias, gate-interleaved
__device__ float d_Upk[(size_t)NG * G4];          // lstm_U packed gate-interleaved (64 MB)
__device__ float d_hbuf[2][(size_t)BB * NG];      // ping-pong hidden state
__device__ float d_cbuf[(size_t)BB * NG];         // cell state
__device__ float d_hs[(size_t)MTR * NG];          // h history [b*T+t, Ng] (210 MB)
__device__ float d_gc[(size_t)MTR * NG];          // g_cells (210 MB)

__device__ __forceinline__ float sigmoidf_(float z) {
    return 1.0f / (1.0f + __expf(-z));
}

// ---------------------------------------------------------------------------
// prep: W2pk[d][n] (gate-interleaved) = sum_g M_W[d][g] * lstm_W[g][j(n)]
//       b2pk[n] = sum_g M_b[g]*lstm_W[g][j] + lstm_b[j]
// packed col n -> original col j = (n&3)*NG + (n>>2)  (quad = i,f,g,o)
// ---------------------------------------------------------------------------
__global__ void prep_w2_k(const float* __restrict__ lstm_W,
                          const float* __restrict__ lstm_b,
                          const float* __restrict__ M_W,
                          const float* __restrict__ M_b) {
    int n = blockIdx.x * blockDim.x + threadIdx.x;
    if (n >= G4) return;
    int j = ((n & 3) << 11) + (n >> 2);
    float w0 = 0.f, w1 = 0.f, bb = 0.f;
#pragma unroll 16
    for (int g = 0; g < NG; g++) {
        float lw = lstm_W[(size_t)g * G4 + j];
        w0 = fmaf(M_W[g],       lw, w0);
        w1 = fmaf(M_W[NG + g],  lw, w1);
        bb = fmaf(M_b[g],       lw, bb);
    }
    d_W2pk[n]      = w0;
    d_W2pk[G4 + n] = w1;
    d_b2pk[n]      = bb + lstm_b[j];
}

// Pack lstm_U into gate-interleaved layout: Upk[k][c*4+q] = U[k][q*NG + c]
__global__ void pack_U_k(const float* __restrict__ U) {
    size_t idx = (size_t)blockIdx.x * blockDim.x + threadIdx.x;
    if (idx >= (size_t)NG * G4) return;
    int k = (int)(idx / G4);
    int n = (int)(idx % G4);
    int q = n & 3, c = n >> 2;
    d_Upk[idx] = U[(size_t)k * G4 + q * NG + c];
}

// ---------------------------------------------------------------------------
// Generic tiled SGEMM: C[M,N] = A[M,K] @ W[K,N]  (both row-major)
// BM=128, BN=64, BK=16, 256 threads, 8x4 register tile per thread.
// Epilogue modes:
//   0 = bias            (enc h0/c0, dec output)
//   1 = relu(bias)      (dense -> g_cells)
//   2 = LSTM gate update (fused x-gate inject + i,f,g,o + c/h update + hs store)
// All dims are exact multiples of the tile sizes for this problem.
// ---------------------------------------------------------------------------
template <int MODE>
__global__ __launch_bounds__(256)
void gemm_k(const float* __restrict__ A, const float* __restrict__ W,
            const float* __restrict__ bias, float* __restrict__ C,
            int M, int N, int K,
            const float* __restrict__ v,       // gate mode: velocities [B,T,2]
            float* __restrict__ c_state,       // gate mode
            float* __restrict__ h_out,         // gate mode
            float* __restrict__ hs,            // gate mode
            int t) {
    __shared__ float As[16][132];   // [k][m], padded to dodge bank conflicts
    __shared__ float Bs[16][64];    // [k][n]

    const int tid = threadIdx.x;
    const int tx = tid & 15;        // 16 column groups
    const int ty = tid >> 4;        // 16 row groups
    const int m0 = blockIdx.y * 128;
    const int n0 = blockIdx.x * 64;

    float acc[8][4];
#pragma unroll
    for (int i = 0; i < 8; i++)
#pragma unroll
        for (int j = 0; j < 4; j++) acc[i][j] = 0.f;

    for (int k0 = 0; k0 < K; k0 += 16) {
        // Load A tile (128x16): 512 float4, 2 per thread, store transposed
#pragma unroll
        for (int it = 0; it < 2; it++) {
            int fid = tid + it * 256;
            int m = fid >> 2;
            int kq = (fid & 3) << 2;
            float4 a4 = *(const float4*)(A + (size_t)(m0 + m) * K + k0 + kq);
            As[kq + 0][m] = a4.x;
            As[kq + 1][m] = a4.y;
            As[kq + 2][m] = a4.z;
            As[kq + 3][m] = a4.w;
        }
        // Load B tile (16x64): 256 float4, 1 per thread
        {
            int kk = tid >> 4;
            int n4 = (tid & 15) << 2;
            *(float4*)&Bs[kk][n4] =
                *(const float4*)(W + (size_t)(k0 + kk) * N + n0 + n4);
        }
        __syncthreads();

#pragma unroll
        for (int k = 0; k < 16; k++) {
            float a[8], b[4];
            *(float4*)(a)     = *(const float4*)&As[k][ty * 4];
            *(float4*)(a + 4) = *(const float4*)&As[k][64 + ty * 4];
            *(float4*)(b)     = *(const float4*)&Bs[k][tx * 4];
#pragma unroll
            for (int i = 0; i < 8; i++)
#pragma unroll
                for (int j = 0; j < 4; j++)
                    acc[i][j] = fmaf(a[i], b[j], acc[i][j]);
        }
        __syncthreads();
    }

    if (MODE == 2) {
        // ---- LSTM gate epilogue ----
        // This thread owns one gate quad (i,f,g,o) at packed cols pc..pc+3
        const int pc = n0 + tx * 4;
        const int gcol = pc >> 2;                      // Ng column
        float4 q0 = *(const float4*)&d_W2pk[pc];       // v0 weights
        float4 q1 = *(const float4*)&d_W2pk[G4 + pc];  // v1 weights
        float4 qb = *(const float4*)&d_b2pk[pc];       // bias
#pragma unroll
        for (int i = 0; i < 8; i++) {
            int b_ = m0 + ((i < 4) ? (ty * 4 + i) : (64 + ty * 4 + i - 4));
            size_t vrow = ((size_t)b_ * TT + t) * 2;
            float v0 = v[vrow + 0];
            float v1 = v[vrow + 1];
            float zi = acc[i][0] + fmaf(v0, q0.x, fmaf(v1, q1.x, qb.x));
            float zf = acc[i][1] + fmaf(v0, q0.y, fmaf(v1, q1.y, qb.y));
            float zg = acc[i][2] + fmaf(v0, q0.z, fmaf(v1, q1.z, qb.z));
            float zo = acc[i][3] + fmaf(v0, q0.w, fmaf(v1, q1.w, qb.w));
            float ig = sigmoidf_(zi);
            float fg = sigmoidf_(zf);
            float gg = fmaxf(zg, 0.f);          // activation='relu' on cell input
            float og = sigmoidf_(zo);
            size_t ci = (size_t)b_ * NG + gcol;
            float cn = fmaf(fg, c_state[ci], ig * gg);
            c_state[ci] = cn;
            float h = og * fmaxf(cn, 0.f);      // recurrent activation relu
            h_out[ci] = h;
            hs[((size_t)b_ * TT + t) * NG + gcol] = h;
        }
    } else {
        // ---- bias / relu+bias epilogue ----
        float4 b4 = *(const float4*)&bias[n0 + tx * 4];
#pragma unroll
        for (int i = 0; i < 8; i++) {
            int m_ = m0 + ((i < 4) ? (ty * 4 + i) : (64 + ty * 4 + i - 4));
            float4 r;
            r.x = acc[i][0] + b4.x;
            r.y = acc[i][1] + b4.y;
            r.z = acc[i][2] + b4.z;
            r.w = acc[i][3] + b4.w;
            if (MODE == 1) {
                r.x = fmaxf(r.x, 0.f);
                r.y = fmaxf(r.y, 0.f);
                r.z = fmaxf(r.z, 0.f);
                r.w = fmaxf(r.w, 0.f);
            }
            *(float4*)(C + (size_t)m_ * N + n0 + tx * 4) = r;
        }
    }
}

// ---------------------------------------------------------------------------
extern "C" void kernel_launch(void* const* d_in, const int* in_sizes, int n_in,
                              void* d_out, int out_size) {
    const float* v       = (const float*)d_in[0];
    const float* p0      = (const float*)d_in[1];
    const float* enc1_W  = (const float*)d_in[2];
    const float* enc1_b  = (const float*)d_in[3];
    const float* enc2_W  = (const float*)d_in[4];
    const float* enc2_b  = (const float*)d_in[5];
    const float* M_W     = (const float*)d_in[6];
    const float* M_b     = (const float*)d_in[7];
    const float* lstm_W  = (const float*)d_in[8];
    const float* lstm_U  = (const float*)d_in[9];
    const float* lstm_b  = (const float*)d_in[10];
    const float* dense_W = (const float*)d_in[11];
    const float* dense_b = (const float*)d_in[12];
    const float* dec_W   = (const float*)d_in[13];
    const float* dec_b   = (const float*)d_in[14];
    float* out = (float*)d_out;

    float *Upk, *hbase, *cp, *hsp, *gp;
    cudaGetSymbolAddress((void**)&Upk,   d_Upk);
    cudaGetSymbolAddress((void**)&hbase, d_hbuf);
    cudaGetSymbolAddress((void**)&cp,    d_cbuf);
    cudaGetSymbolAddress((void**)&hsp,   d_hs);
    cudaGetSymbolAddress((void**)&gp,    d_gc);
    float* hping[2] = { hbase, hbase + (size_t)BB * NG };

    // 1) Collapse v->gate weights (rank-2 trick) + pack U gate-interleaved
    prep_w2_k<<<G4 / 256, 256>>>(lstm_W, lstm_b, M_W, M_b);
    pack_U_k<<<(int)(((size_t)NG * G4) / 256), 256>>>(lstm_U);

    // 2) Initial state: h0 = p0@enc1_W + enc1_b ; c0 = p0@enc2_W + enc2_b
    gemm_k<0><<<dim3(NG / 64, BB / 128), 256>>>(
        p0, enc1_W, enc1_b, hping[0], BB, NG, NP,
        nullptr, nullptr, nullptr, nullptr, 0);
    gemm_k<0><<<dim3(NG / 64, BB / 128), 256>>>(
        p0, enc2_W, enc2_b, cp, BB, NG, NP,
        nullptr, nullptr, nullptr, nullptr, 0);

    // 3) Recurrence: 100 sequential gate GEMMs with fused epilogue
    for (int t = 0; t < TT; t++) {
        gemm_k<2><<<dim3(G4 / 64, BB / 128), 256>>>(
            hping[t & 1], Upk, nullptr, nullptr, BB, G4, NG,
            v, cp, hping[(t + 1) & 1], hsp, t);
    }

    // 4) dense: g = relu(hs @ dense_W + dense_b)
    gemm_k<1><<<dim3(NG / 64, MTR / 128), 256>>>(
        hsp, dense_W, dense_b, gp, MTR, NG, NG,
        nullptr, nullptr, nullptr, nullptr, 0);

    // 5) dec: out = g @ dec_W + dec_b
    gemm_k<0><<<dim3(NP / 64, MTR / 128), 256>>>(
        gp, dec_W, dec_b, out, MTR, NP, NG,
        nullptr, nullptr, nullptr, nullptr, 0);
}

// round 3
// speedup vs baseline: 2.6383x; 2.6383x over previous
#include <cuda_runtime.h>
#include <cuda_bf16.h>
#include <cstdint>

// Problem constants
#define BB   256
#define TT   100
#define NG   2048
#define NP   512
#define G4   8192          // 4*NG
#define MTR  (BB * TT)     // 25600 rows for dense/dec stages

// ---------------------------------------------------------------------------
// Static device scratch (aligned for float4 / cp.async)
// ---------------------------------------------------------------------------
__device__ __align__(128) float d_W2pk[2 * G4];                 // collapsed v->gates weights (gate-interleaved)
__device__ __align__(128) float d_b2pk[G4];                     // collapsed bias (gate-interleaved)
__device__ __align__(128) __nv_bfloat16 d_Uhi[(size_t)G4 * NG]; // U^T split-hi [n][k], gate-interleaved n
__device__ __align__(128) __nv_bfloat16 d_Ulo[(size_t)G4 * NG];
__device__ __align__(128) __nv_bfloat16 d_DWhi[(size_t)NG * NG];// dense_W^T split
__device__ __align__(128) __nv_bfloat16 d_DWlo[(size_t)NG * NG];
__device__ __align__(128) __nv_bfloat16 d_DChi[(size_t)NP * NG];// dec_W^T split
__device__ __align__(128) __nv_bfloat16 d_DClo[(size_t)NP * NG];
__device__ __align__(128) __nv_bfloat16 d_hhi[2][(size_t)BB * NG];
__device__ __align__(128) __nv_bfloat16 d_hlo[2][(size_t)BB * NG];
__device__ __align__(128) float d_cbuf[(size_t)BB * NG];
__device__ __align__(128) __nv_bfloat16 d_hshi[(size_t)MTR * NG];
__device__ __align__(128) __nv_bfloat16 d_hslo[(size_t)MTR * NG];
__device__ __align__(128) __nv_bfloat16 d_ghi[(size_t)MTR * NG];
__device__ __align__(128) __nv_bfloat16 d_glo[(size_t)MTR * NG];

__device__ __forceinline__ float sigmoidf_(float z) {
    return 1.0f / (1.0f + __expf(-z));
}

// ---------------------------------------------------------------------------
// PTX helpers (plain sm_103-legal only: cp.async / ldmatrix / mma.sync)
// ---------------------------------------------------------------------------
__device__ __forceinline__ uint32_t smem_u32(const void* p) {
    uint32_t a;
    asm("{ .reg .u64 t; cvta.to.shared.u64 t, %1; cvt.u32.u64 %0, t; }" : "=r"(a) : "l"(p));
    return a;
}
#define CP_ASYNC16(dst, src) \
    asm volatile("cp.async.cg.shared.global [%0], [%1], 16;" :: "r"(dst), "l"(src) : "memory")
#define CP_COMMIT()  asm volatile("cp.async.commit_group;" ::: "memory")
#define CP_WAIT(n)   asm volatile("cp.async.wait_group %0;" :: "n"(n) : "memory")

#define LDMX4(r0, r1, r2, r3, addr) \
    asm volatile("ldmatrix.sync.aligned.m8n8.x4.shared.b16 {%0,%1,%2,%3}, [%4];" \
        : "=r"(r0), "=r"(r1), "=r"(r2), "=r"(r3) : "r"(addr))

#define MMA16816(d, a, b0, b1) \
    asm volatile("mma.sync.aligned.m16n8k16.row.col.f32.bf16.bf16.f32 " \
        "{%0,%1,%2,%3}, {%4,%5,%6,%7}, {%8,%9}, {%0,%1,%2,%3};" \
        : "+f"((d)[0]), "+f"((d)[1]), "+f"((d)[2]), "+f"((d)[3]) \
        : "r"((a)[0]), "r"((a)[1]), "r"((a)[2]), "r"((a)[3]), "r"(b0), "r"(b1))

// swizzled byte offset inside a [128 rows x 128B] tile
__device__ __forceinline__ uint32_t swz(int row, int colbyte) {
    return (uint32_t)((row << 7) + (colbyte ^ ((row & 7) << 4)));
}

// ---------------------------------------------------------------------------
// prep: collapse v->gates (rank-2 trick), gate-interleaved
// ---------------------------------------------------------------------------
__global__ void prep_w2_k(const float* __restrict__ lstm_W,
                          const float* __restrict__ lstm_b,
                          const float* __restrict__ M_W,
                          const float* __restrict__ M_b) {
    int n = blockIdx.x * blockDim.x + threadIdx.x;
    if (n >= G4) return;
    int j = ((n & 3) << 11) + (n >> 2);
    float w0 = 0.f, w1 = 0.f, bb = 0.f;
#pragma unroll 16
    for (int g = 0; g < NG; g++) {
        float lw = lstm_W[(size_t)g * G4 + j];
        w0 = fmaf(M_W[g],      lw, w0);
        w1 = fmaf(M_W[NG + g], lw, w1);
        bb = fmaf(M_b[g],      lw, bb);
    }
    d_W2pk[n]      = w0;
    d_W2pk[G4 + n] = w1;
    d_b2pk[n]      = bb + lstm_b[j];
}

// ---------------------------------------------------------------------------
// Transpose + split: dst_hi/lo[n][k] (bf16) from src[k][j] (fp32), n = map(j)
// ---------------------------------------------------------------------------
template <bool GATE>
__global__ void transp_split_k(const float* __restrict__ src,
                               __nv_bfloat16* __restrict__ hi,
                               __nv_bfloat16* __restrict__ lo,
                               int K, int N) {
    __shared__ float tile[32][33];
    int k0 = blockIdx.x * 32, j0 = blockIdx.y * 32;
    int tx = threadIdx.x, ty = threadIdx.y;   // (32, 8)
#pragma unroll
    for (int i = 0; i < 4; i++)
        tile[ty + i * 8][tx] = src[(size_t)(k0 + ty + i * 8) * N + j0 + tx];
    __syncthreads();
#pragma unroll
    for (int i = 0; i < 4; i++) {
        int j = j0 + ty + i * 8;
        int n = GATE ? ((j & (NG - 1)) * 4 + (j >> 11)) : j;
        float x = tile[tx][ty + i * 8];       // src[k0+tx][j]
        __nv_bfloat16 h = __float2bfloat16(x);
        hi[(size_t)n * K + k0 + tx] = h;
        lo[(size_t)n * K + k0 + tx] = __float2bfloat16(x - __bfloat162float(h));
    }
}

// ---------------------------------------------------------------------------
// SIMT GEMM for the small encoder stage (M=256, N=2048, K=512)
// MODE 0: fp32 bias out.  MODE 3: bias out as split bf16 (hi/lo).
// ---------------------------------------------------------------------------
template <int MODE>
__global__ __launch_bounds__(256)
void gemm_k(const float* __restrict__ A, const float* __restrict__ W,
            const float* __restrict__ bias, float* __restrict__ C,
            __nv_bfloat16* __restrict__ o_hi, __nv_bfloat16* __restrict__ o_lo,
            int M, int N, int K) {
    __shared__ float As[16][132];
    __shared__ float Bs[16][64];
    const int tid = threadIdx.x;
    const int tx = tid & 15;
    const int ty = tid >> 4;
    const int m0 = blockIdx.y * 128;
    const int n0 = blockIdx.x * 64;

    float acc[8][4];
#pragma unroll
    for (int i = 0; i < 8; i++)
#pragma unroll
        for (int j = 0; j < 4; j++) acc[i][j] = 0.f;

    for (int k0 = 0; k0 < K; k0 += 16) {
#pragma unroll
        for (int it = 0; it < 2; it++) {
            int fid = tid + it * 256;
            int m = fid >> 2;
            int kq = (fid & 3) << 2;
            float4 a4 = *(const float4*)(A + (size_t)(m0 + m) * K + k0 + kq);
            As[kq + 0][m] = a4.x; As[kq + 1][m] = a4.y;
            As[kq + 2][m] = a4.z; As[kq + 3][m] = a4.w;
        }
        {
            int kk = tid >> 4;
            int n4 = (tid & 15) << 2;
            *(float4*)&Bs[kk][n4] = *(const float4*)(W + (size_t)(k0 + kk) * N + n0 + n4);
        }
        __syncthreads();
#pragma unroll
        for (int k = 0; k < 16; k++) {
            float a[8], b[4];
            *(float4*)(a)     = *(const float4*)&As[k][ty * 4];
            *(float4*)(a + 4) = *(const float4*)&As[k][64 + ty * 4];
            *(float4*)(b)     = *(const float4*)&Bs[k][tx * 4];
#pragma unroll
            for (int i = 0; i < 8; i++)
#pragma unroll
                for (int j = 0; j < 4; j++)
                    acc[i][j] = fmaf(a[i], b[j], acc[i][j]);
        }
        __syncthreads();
    }

    float4 b4 = *(const float4*)&bias[n0 + tx * 4];
#pragma unroll
    for (int i = 0; i < 8; i++) {
        int m_ = m0 + ((i < 4) ? (ty * 4 + i) : (64 + ty * 4 + i - 4));
#pragma unroll
        for (int j = 0; j < 4; j++) {
            float r = acc[i][j] + ((j == 0) ? b4.x : (j == 1) ? b4.y : (j == 2) ? b4.z : b4.w);
            size_t idx = (size_t)m_ * N + n0 + tx * 4 + j;
            if (MODE == 0) {
                C[idx] = r;
            } else {
                __nv_bfloat16 h = __float2bfloat16(r);
                o_hi[idx] = h;
                o_lo[idx] = __float2bfloat16(r - __bfloat162float(h));
            }
        }
    }
}

// ---------------------------------------------------------------------------
// HMMA split-bf16 GEMM.  CTA tile 128x128, K chunk 64, double-buffered smem.
// A: [rows][K] bf16 hi/lo row-major.  B: [N][K] bf16 hi/lo row-major.
// Computes Ahi@Bhi^T + Ahi@Blo^T + Alo@Bhi^T (fp32 accum).
// MODE 0: fp32 bias out (dec).  MODE 1: relu+bias -> split bf16 (dense).
// MODE 2: fused LSTM gate epilogue.
// 8 warps: warp grid 2(m) x 4(n), warp tile 64x32.
// smem stage: Ahi(16K) Alo(16K) Bhi(16K) Blo(16K) = 64K; x2 stages = 128K.
// ---------------------------------------------------------------------------
template <int MODE>
__global__ __launch_bounds__(256, 1)
void hmma_gemm(const __nv_bfloat16* __restrict__ Ahi, const __nv_bfloat16* __restrict__ Alo,
               const __nv_bfloat16* __restrict__ Bhi, const __nv_bfloat16* __restrict__ Blo,
               const float* __restrict__ bias, float* __restrict__ Cout,
               int N, int K,
               const float* __restrict__ v, float* __restrict__ c_state,
               __nv_bfloat16* __restrict__ o_hi, __nv_bfloat16* __restrict__ o_lo,
               __nv_bfloat16* __restrict__ hs_hi, __nv_bfloat16* __restrict__ hs_lo,
               int t) {
    extern __shared__ char smem[];
    const uint32_t sb = smem_u32(smem);
    const int tid  = threadIdx.x;
    const int lane = tid & 31;
    const int wid  = tid >> 5;
    const int wm   = wid >> 2;          // 0..1
    const int wn   = wid & 3;           // 0..3
    const int n0 = blockIdx.x * 128;
    const int m0 = blockIdx.y * 128;
    const int NC = K >> 6;              // K/64 chunks

    // lane-fixed ldmatrix geometry
    const int a_r  = (lane & 7) + ((lane >> 3) & 1) * 8;
    const int a_cb = ((lane >> 4) & 1) * 16;
    const int b_r  = (lane & 7) + ((lane >> 4) & 1) * 8;
    const int b_cb = ((lane >> 3) & 1) * 16;

    float acc[4][4][4];
#pragma unroll
    for (int i = 0; i < 4; i++)
#pragma unroll
        for (int j = 0; j < 4; j++)
#pragma unroll
            for (int r = 0; r < 4; r++) acc[i][j][r] = 0.f;

    auto load_stage = [&](int p, int k0) {
        const __nv_bfloat16* srcs[4] = {Ahi, Alo, Bhi, Blo};
        const int r0s[4] = {m0, m0, n0, n0};
#pragma unroll
        for (int tm = 0; tm < 4; tm++) {
            uint32_t tb = sb + (uint32_t)p * 65536u + (uint32_t)tm * 16384u;
#pragma unroll
            for (int i = 0; i < 4; i++) {
                int idx = tid + i * 256;
                int row = idx >> 3;
                int c   = idx & 7;
                const void* g = (const void*)(srcs[tm] + (size_t)(r0s[tm] + row) * K + k0 + c * 8);
                CP_ASYNC16(tb + swz(row, c * 16), g);
            }
        }
    };

    load_stage(0, 0);
    CP_COMMIT();
    if (NC > 1) { load_stage(1, 64); }
    CP_COMMIT();

    for (int it = 0; it < NC; it++) {
        if (it == NC - 1) { CP_WAIT(0); } else { CP_WAIT(1); }
        __syncthreads();
        uint32_t stg = sb + (uint32_t)(it & 1) * 65536u;

#pragma unroll 1
        for (int kk = 0; kk < 4; kk++) {
            uint32_t ah[4][4], al[4][4], bh[2][4], bl[2][4];
#pragma unroll
            for (int mi = 0; mi < 4; mi++) {
                uint32_t off = swz(wm * 64 + mi * 16 + a_r, kk * 32 + a_cb);
                LDMX4(ah[mi][0], ah[mi][1], ah[mi][2], ah[mi][3], stg + off);
                LDMX4(al[mi][0], al[mi][1], al[mi][2], al[mi][3], stg + 16384u + off);
            }
#pragma unroll
            for (int bt = 0; bt < 2; bt++) {
                uint32_t off = swz(wn * 32 + bt * 16 + b_r, kk * 32 + b_cb);
                LDMX4(bh[bt][0], bh[bt][1], bh[bt][2], bh[bt][3], stg + 32768u + off);
                LDMX4(bl[bt][0], bl[bt][1], bl[bt][2], bl[bt][3], stg + 49152u + off);
            }
#pragma unroll
            for (int mi = 0; mi < 4; mi++)
#pragma unroll
                for (int ni = 0; ni < 4; ni++) {
                    int bt = ni >> 1, pr = (ni & 1) * 2;
                    MMA16816(acc[mi][ni], ah[mi], bh[bt][pr], bh[bt][pr + 1]);
                    MMA16816(acc[mi][ni], ah[mi], bl[bt][pr], bl[bt][pr + 1]);
                    MMA16816(acc[mi][ni], al[mi], bh[bt][pr], bh[bt][pr + 1]);
                }
        }
        __syncthreads();
        if (it + 2 < NC) { load_stage(it & 1, (it + 2) * 64); }
        CP_COMMIT();
    }

    // ---- Epilogue ----
    const int gi = lane >> 2;
    const int ci = lane & 3;

    if (MODE == 2) {
        const bool isIF = (lane & 1) == 0;
        // per-mi row (this lane processes row_a if IF-lane else row_a+8)
        int rowm[4];
        float vv0[4], vv1[4];
#pragma unroll
        for (int mi = 0; mi < 4; mi++) {
            rowm[mi] = m0 + wm * 64 + mi * 16 + gi + (isIF ? 0 : 8);
            size_t vr = ((size_t)rowm[mi] * TT + t) * 2;
            vv0[mi] = v[vr];
            vv1[mi] = v[vr + 1];
        }
#pragma unroll
        for (int mi = 0; mi < 4; mi++)
#pragma unroll
            for (int ni = 0; ni < 4; ni++) {
                float c0 = acc[mi][ni][0], c1 = acc[mi][ni][1];
                float c2 = acc[mi][ni][2], c3 = acc[mi][ni][3];
                float o0 = __shfl_xor_sync(0xFFFFFFFFu, c0, 1);
                float o1 = __shfl_xor_sync(0xFFFFFFFFu, c1, 1);
                float o2 = __shfl_xor_sync(0xFFFFFFFFu, c2, 1);
                float o3 = __shfl_xor_sync(0xFFFFFFFFu, c3, 1);
                float zi = isIF ? c0 : o2;
                float zf = isIF ? c1 : o3;
                float zg = isIF ? o0 : c2;
                float zo = isIF ? o1 : c3;
                int row  = rowm[mi];
                int qcol = n0 + wn * 32 + ni * 8 + (ci >> 1) * 4;
                float4 q0 = *(const float4*)&d_W2pk[qcol];
                float4 q1 = *(const float4*)&d_W2pk[G4 + qcol];
                float4 qb = *(const float4*)&d_b2pk[qcol];
                zi += fmaf(vv0[mi], q0.x, fmaf(vv1[mi], q1.x, qb.x));
                zf += fmaf(vv0[mi], q0.y, fmaf(vv1[mi], q1.y, qb.y));
                zg += fmaf(vv0[mi], q0.z, fmaf(vv1[mi], q1.z, qb.z));
                zo += fmaf(vv0[mi], q0.w, fmaf(vv1[mi], q1.w, qb.w));
                float ig = sigmoidf_(zi);
                float fg = sigmoidf_(zf);
                float gg = fmaxf(zg, 0.f);
                float og = sigmoidf_(zo);
                int gcol = qcol >> 2;
                size_t cidx = (size_t)row * NG + gcol;
                float cn = fmaf(fg, c_state[cidx], ig * gg);
                c_state[cidx] = cn;
                float h = og * fmaxf(cn, 0.f);
                __nv_bfloat16 hh = __float2bfloat16(h);
                __nv_bfloat16 hl = __float2bfloat16(h - __bfloat162float(hh));
                o_hi[cidx] = hh;
                o_lo[cidx] = hl;
                size_t hsx = ((size_t)row * TT + t) * (size_t)NG + gcol;
                hs_hi[hsx] = hh;
                hs_lo[hsx] = hl;
            }
    } else {
#pragma unroll
        for (int mi = 0; mi < 4; mi++)
#pragma unroll
            for (int ni = 0; ni < 4; ni++) {
                int row0 = m0 + wm * 64 + mi * 16 + gi;
                int col  = n0 + wn * 32 + ni * 8 + ci * 2;
                float bx = bias[col], by = bias[col + 1];
                float r0 = acc[mi][ni][0] + bx, r1 = acc[mi][ni][1] + by;
                float r2 = acc[mi][ni][2] + bx, r3 = acc[mi][ni][3] + by;
                if (MODE == 0) {
                    *(float2*)(Cout + (size_t)row0 * N + col)       = make_float2(r0, r1);
                    *(float2*)(Cout + (size_t)(row0 + 8) * N + col) = make_float2(r2, r3);
                } else {
                    r0 = fmaxf(r0, 0.f); r1 = fmaxf(r1, 0.f);
                    r2 = fmaxf(r2, 0.f); r3 = fmaxf(r3, 0.f);
                    __nv_bfloat16 h0 = __float2bfloat16(r0), h1 = __float2bfloat16(r1);
                    __nv_bfloat16 h2 = __float2bfloat16(r2), h3 = __float2bfloat16(r3);
                    size_t i0 = (size_t)row0 * N + col;
                    size_t i1 = (size_t)(row0 + 8) * N + col;
                    *(__nv_bfloat162*)(o_hi + i0) = __nv_bfloat162(h0, h1);
                    *(__nv_bfloat162*)(o_hi + i1) = __nv_bfloat162(h2, h3);
                    *(__nv_bfloat162*)(o_lo + i0) = __nv_bfloat162(
                        __float2bfloat16(r0 - __bfloat162float(h0)),
                        __float2bfloat16(r1 - __bfloat162float(h1)));
                    *(__nv_bfloat162*)(o_lo + i1) = __nv_bfloat162(
                        __float2bfloat16(r2 - __bfloat162float(h2)),
                        __float2bfloat16(r3 - __bfloat162float(h3)));
                }
            }
    }
}

// ---------------------------------------------------------------------------
extern "C" void kernel_launch(void* const* d_in, const int* in_sizes, int n_in,
                              void* d_out, int out_size) {
    const float* v       = (const float*)d_in[0];
    const float* p0      = (const float*)d_in[1];
    const float* enc1_W  = (const float*)d_in[2];
    const float* enc1_b  = (const float*)d_in[3];
    const float* enc2_W  = (const float*)d_in[4];
    const float* enc2_b  = (const float*)d_in[5];
    const float* M_W     = (const float*)d_in[6];
    const float* M_b     = (const float*)d_in[7];
    const float* lstm_W  = (const float*)d_in[8];
    const float* lstm_U  = (const float*)d_in[9];
    const float* lstm_b  = (const float*)d_in[10];
    const float* dense_W = (const float*)d_in[11];
    const float* dense_b = (const float*)d_in[12];
    const float* dec_W   = (const float*)d_in[13];
    const float* dec_b   = (const float*)d_in[14];
    float* out = (float*)d_out;

    __nv_bfloat16 *Uhi, *Ulo, *DWhi, *DWlo, *DChi, *DClo;
    __nv_bfloat16 *hhi, *hlo, *hshi, *hslo, *ghi, *glo;
    float *cp;
    cudaGetSymbolAddress((void**)&Uhi,  d_Uhi);
    cudaGetSymbolAddress((void**)&Ulo,  d_Ulo);
    cudaGetSymbolAddress((void**)&DWhi, d_DWhi);
    cudaGetSymbolAddress((void**)&DWlo, d_DWlo);
    cudaGetSymbolAddress((void**)&DChi, d_DChi);
    cudaGetSymbolAddress((void**)&DClo, d_DClo);
    cudaGetSymbolAddress((void**)&hhi,  d_hhi);
    cudaGetSymbolAddress((void**)&hlo,  d_hlo);
    cudaGetSymbolAddress((void**)&hshi, d_hshi);
    cudaGetSymbolAddress((void**)&hslo, d_hslo);
    cudaGetSymbolAddress((void**)&ghi,  d_ghi);
    cudaGetSymbolAddress((void**)&glo,  d_glo);
    cudaGetSymbolAddress((void**)&cp,   d_cbuf);

    const int SMEMSZ = 2 * 65536;  // 128 KB double-buffered stage
    cudaFuncSetAttribute(hmma_gemm<0>, cudaFuncAttributeMaxDynamicSharedMemorySize, SMEMSZ);
    cudaFuncSetAttribute(hmma_gemm<1>, cudaFuncAttributeMaxDynamicSharedMemorySize, SMEMSZ);
    cudaFuncSetAttribute(hmma_gemm<2>, cudaFuncAttributeMaxDynamicSharedMemorySize, SMEMSZ);

    // 1) Weight prep: rank-2 collapse of v->gates; transpose+split U/dense/dec
    prep_w2_k<<<G4 / 256, 256>>>(lstm_W, lstm_b, M_W, M_b);
    transp_split_k<true ><<<dim3(NG / 32, G4 / 32), dim3(32, 8)>>>(lstm_U,  Uhi,  Ulo,  NG, G4);
    transp_split_k<false><<<dim3(NG / 32, NG / 32), dim3(32, 8)>>>(dense_W, DWhi, DWlo, NG, NG);
    transp_split_k<false><<<dim3(NG / 32, NP / 32), dim3(32, 8)>>>(dec_W,   DChi, DClo, NG, NP);

    // 2) Initial state: h0 (split bf16), c0 (fp32)
    gemm_k<3><<<dim3(NG / 64, BB / 128), 256>>>(p0, enc1_W, enc1_b, nullptr, hhi, hlo, BB, NG, NP);
    gemm_k<0><<<dim3(NG / 64, BB / 128), 256>>>(p0, enc2_W, enc2_b, cp, nullptr, nullptr, BB, NG, NP);

    // 3) Recurrence: 100 HMMA steps with fused gate epilogue (1 wave each)
    const size_t HP = (size_t)BB * NG;
    for (int tstep = 0; tstep < TT; tstep++) {
        int pi = tstep & 1, po = (tstep + 1) & 1;
        hmma_gemm<2><<<dim3(G4 / 128, BB / 128), 256, SMEMSZ>>>(
            hhi + pi * HP, hlo + pi * HP, Uhi, Ulo, nullptr, nullptr, G4, NG,
            v, cp, hhi + po * HP, hlo + po * HP, hshi, hslo, tstep);
    }

    // 4) dense: g = relu(hs @ dense_W + b) -> split bf16
    hmma_gemm<1><<<dim3(NG / 128, MTR / 128), 256, SMEMSZ>>>(
        hshi, hslo, DWhi, DWlo, dense_b, nullptr, NG, NG,
        nullptr, nullptr, ghi, glo, nullptr, nullptr, 0);

    // 5) dec: out = g @ dec_W + b -> fp32
    hmma_gemm<0><<<dim3(NP / 128, MTR / 128), 256, SMEMSZ>>>(
        ghi, glo, DChi, DClo, dec_b, out, NP, NG,
        nullptr, nullptr, nullptr, nullptr, nullptr, nullptr, 0);
}

// round 4
// speedup vs baseline: 2.6736x; 1.0134x over previous
#include <cuda_runtime.h>
#include <cuda_bf16.h>
#include <cstdint>

// Problem constants
#define BB   256
#define TT   100
#define NG   2048
#define NP   512
#define G4   8192          // 4*NG
#define MTR  (BB * TT)     // 25600 rows for dense/dec stages

// ---------------------------------------------------------------------------
// Static device scratch
// ---------------------------------------------------------------------------
__device__ __align__(128) float d_W2pk[2 * G4];
__device__ __align__(128) float d_b2pk[G4];
__device__ __align__(128) __nv_bfloat16 d_Uhi[(size_t)G4 * NG];
__device__ __align__(128) __nv_bfloat16 d_Ulo[(size_t)G4 * NG];
__device__ __align__(128) __nv_bfloat16 d_DWhi[(size_t)NG * NG];
__device__ __align__(128) __nv_bfloat16 d_DWlo[(size_t)NG * NG];
__device__ __align__(128) __nv_bfloat16 d_DChi[(size_t)NP * NG];
__device__ __align__(128) __nv_bfloat16 d_DClo[(size_t)NP * NG];
__device__ __align__(128) __nv_bfloat16 d_hhi[2][(size_t)BB * NG];
__device__ __align__(128) __nv_bfloat16 d_hlo[2][(size_t)BB * NG];
__device__ __align__(128) float d_cbuf[(size_t)BB * NG];
__device__ __align__(128) __nv_bfloat16 d_hshi[(size_t)MTR * NG];
__device__ __align__(128) __nv_bfloat16 d_hslo[(size_t)MTR * NG];
__device__ __align__(128) __nv_bfloat16 d_ghi[(size_t)MTR * NG];
__device__ __align__(128) __nv_bfloat16 d_glo[(size_t)MTR * NG];

__device__ __forceinline__ float sigmoidf_(float z) {
    return 1.0f / (1.0f + __expf(-z));
}

// ---------------------------------------------------------------------------
// PTX helpers (plain sm_103-legal: cp.async / ldmatrix / mma.sync)
// ---------------------------------------------------------------------------
__device__ __forceinline__ uint32_t smem_u32(const void* p) {
    uint32_t a;
    asm("{ .reg .u64 t; cvta.to.shared.u64 t, %1; cvt.u32.u64 %0, t; }" : "=r"(a) : "l"(p));
    return a;
}
#define CP_ASYNC16(dst, src) \
    asm volatile("cp.async.cg.shared.global [%0], [%1], 16;" :: "r"(dst), "l"(src) : "memory")
#define CP_COMMIT()  asm volatile("cp.async.commit_group;" ::: "memory")
#define CP_WAIT(n)   asm volatile("cp.async.wait_group %0;" :: "n"(n) : "memory")

#define LDMX4(r0, r1, r2, r3, addr) \
    asm volatile("ldmatrix.sync.aligned.m8n8.x4.shared.b16 {%0,%1,%2,%3}, [%4];" \
        : "=r"(r0), "=r"(r1), "=r"(r2), "=r"(r3) : "r"(addr))

#define MMA16816(d, a, b0, b1) \
    asm volatile("mma.sync.aligned.m16n8k16.row.col.f32.bf16.bf16.f32 " \
        "{%0,%1,%2,%3}, {%4,%5,%6,%7}, {%8,%9}, {%0,%1,%2,%3};" \
        : "+f"((d)[0]), "+f"((d)[1]), "+f"((d)[2]), "+f"((d)[3]) \
        : "r"((a)[0]), "r"((a)[1]), "r"((a)[2]), "r"((a)[3]), "r"(b0), "r"(b1))

// swizzled byte offset inside a [rows x 128B] tile
__device__ __forceinline__ uint32_t swz(int row, int colbyte) {
    return (uint32_t)((row << 7) + (colbyte ^ ((row & 7) << 4)));
}

// ---------------------------------------------------------------------------
// prep: collapse v->gates (rank-2 trick), gate-interleaved; COALESCED reads
// ---------------------------------------------------------------------------
__global__ void prep_w2_k(const float* __restrict__ lstm_W,
                          const float* __restrict__ lstm_b,
                          const float* __restrict__ M_W,
                          const float* __restrict__ M_b) {
    int j = blockIdx.x * blockDim.x + threadIdx.x;   // original column
    if (j >= G4) return;
    float w0 = 0.f, w1 = 0.f, bb = 0.f;
#pragma unroll 8
    for (int g = 0; g < NG; g++) {
        float lw = lstm_W[(size_t)g * G4 + j];       // coalesced across warp
        w0 = fmaf(M_W[g],      lw, w0);
        w1 = fmaf(M_W[NG + g], lw, w1);
        bb = fmaf(M_b[g],      lw, bb);
    }
    int n = (j & (NG - 1)) * 4 + (j >> 11);          // gate-interleaved index
    d_W2pk[n]      = w0;
    d_W2pk[G4 + n] = w1;
    d_b2pk[n]      = bb + lstm_b[j];
}

// ---------------------------------------------------------------------------
// Fused transpose+split for U (gate-interleaved), dense_W, dec_W. 1 launch.
// 1D grid decode: [0,16384) U ; [16384,20480) dense ; [20480,21504) dec
// ---------------------------------------------------------------------------
__global__ void transp_split_all(const float* __restrict__ U,
                                 const float* __restrict__ DW,
                                 const float* __restrict__ DC) {
    __shared__ float tile[32][33];
    int bid = blockIdx.x;
    const float* src;
    __nv_bfloat16 *hi, *lo;
    int N, bx, by;
    bool gate = false;
    if (bid < 16384) {
        src = U;  hi = d_Uhi;  lo = d_Ulo;  N = G4; gate = true;
        bx = bid & 63; by = bid >> 6;
    } else if (bid < 20480) {
        int l = bid - 16384;
        src = DW; hi = d_DWhi; lo = d_DWlo; N = NG;
        bx = l & 63; by = l >> 6;
    } else {
        int l = bid - 20480;
        src = DC; hi = d_DChi; lo = d_DClo; N = NP;
        bx = l & 63; by = l >> 6;
    }
    const int K = NG;
    int k0 = bx * 32, j0 = by * 32;
    int tx = threadIdx.x, ty = threadIdx.y;   // (32, 8)
#pragma unroll
    for (int i = 0; i < 4; i++)
        tile[ty + i * 8][tx] = src[(size_t)(k0 + ty + i * 8) * N + j0 + tx];
    __syncthreads();
#pragma unroll
    for (int i = 0; i < 4; i++) {
        int j = j0 + ty + i * 8;
        int n = gate ? ((j & (NG - 1)) * 4 + (j >> 11)) : j;
        float x = tile[tx][ty + i * 8];
        __nv_bfloat16 h = __float2bfloat16(x);
        hi[(size_t)n * K + k0 + tx] = h;
        lo[(size_t)n * K + k0 + tx] = __float2bfloat16(x - __bfloat162float(h));
    }
}

// ---------------------------------------------------------------------------
// Fused encoder: z=0 -> h0 = p0@enc1_W+b (split bf16); z=1 -> c0 fp32
// ---------------------------------------------------------------------------
__global__ __launch_bounds__(256)
void enc_k(const float* __restrict__ p0,
           const float* __restrict__ W1, const float* __restrict__ b1,
           const float* __restrict__ W2, const float* __restrict__ b2,
           __nv_bfloat16* __restrict__ o_hi, __nv_bfloat16* __restrict__ o_lo,
           float* __restrict__ c0) {
    __shared__ float As[16][132];
    __shared__ float Bs[16][64];
    const int z = blockIdx.z;
    const float* A = p0;
    const float* W = z ? W2 : W1;
    const float* bias = z ? b2 : b1;
    const int M = BB, N = NG, K = NP;
    const int tid = threadIdx.x;
    const int tx = tid & 15;
    const int ty = tid >> 4;
    const int m0 = blockIdx.y * 128;
    const int n0 = blockIdx.x * 64;

    float acc[8][4];
#pragma unroll
    for (int i = 0; i < 8; i++)
#pragma unroll
        for (int j = 0; j < 4; j++) acc[i][j] = 0.f;

    for (int k0 = 0; k0 < K; k0 += 16) {
#pragma unroll
        for (int it = 0; it < 2; it++) {
            int fid = tid + it * 256;
            int m = fid >> 2;
            int kq = (fid & 3) << 2;
            float4 a4 = *(const float4*)(A + (size_t)(m0 + m) * K + k0 + kq);
            As[kq + 0][m] = a4.x; As[kq + 1][m] = a4.y;
            As[kq + 2][m] = a4.z; As[kq + 3][m] = a4.w;
        }
        {
            int kk = tid >> 4;
            int n4 = (tid & 15) << 2;
            *(float4*)&Bs[kk][n4] = *(const float4*)(W + (size_t)(k0 + kk) * N + n0 + n4);
        }
        __syncthreads();
#pragma unroll
        for (int k = 0; k < 16; k++) {
            float a[8], b[4];
            *(float4*)(a)     = *(const float4*)&As[k][ty * 4];
            *(float4*)(a + 4) = *(const float4*)&As[k][64 + ty * 4];
            *(float4*)(b)     = *(const float4*)&Bs[k][tx * 4];
#pragma unroll
            for (int i = 0; i < 8; i++)
#pragma unroll
                for (int j = 0; j < 4; j++)
                    acc[i][j] = fmaf(a[i], b[j], acc[i][j]);
        }
        __syncthreads();
    }

    float4 b4 = *(const float4*)&bias[n0 + tx * 4];
#pragma unroll
    for (int i = 0; i < 8; i++) {
        int m_ = m0 + ((i < 4) ? (ty * 4 + i) : (64 + ty * 4 + i - 4));
#pragma unroll
        for (int j = 0; j < 4; j++) {
            float r = acc[i][j] + ((j == 0) ? b4.x : (j == 1) ? b4.y : (j == 2) ? b4.z : b4.w);
            size_t idx = (size_t)m_ * N + n0 + tx * 4 + j;
            if (z) {
                c0[idx] = r;
            } else {
                __nv_bfloat16 h = __float2bfloat16(r);
                o_hi[idx] = h;
                o_lo[idx] = __float2bfloat16(r - __bfloat162float(h));
            }
        }
    }
}

// ---------------------------------------------------------------------------
// HMMA split-bf16 GEMM, 3-stage cp.async pipeline.
// CTA tile 128x128, K chunk 64. Stage = Ahi|Alo|Bhi|Blo (4 x 16KB) = 64KB x3.
// Computes Ahi@Bhi^T + Ahi@Blo^T + Alo@Bhi^T (fp32 accum).
// MODE 0: fp32 bias out.  MODE 1: relu+bias -> split bf16.  MODE 2: LSTM gate.
// ---------------------------------------------------------------------------
template <int MODE>
__global__ __launch_bounds__(256, 1)
void hmma_gemm(const __nv_bfloat16* __restrict__ Ahi, const __nv_bfloat16* __restrict__ Alo,
               const __nv_bfloat16* __restrict__ Bhi, const __nv_bfloat16* __restrict__ Blo,
               const float* __restrict__ bias, float* __restrict__ Cout,
               int N, int K,
               const float* __restrict__ v, float* __restrict__ c_state,
               __nv_bfloat16* __restrict__ o_hi, __nv_bfloat16* __restrict__ o_lo,
               __nv_bfloat16* __restrict__ hs_hi, __nv_bfloat16* __restrict__ hs_lo,
               int t) {
    extern __shared__ char smem[];
    const uint32_t sb = smem_u32(smem);
    const int tid  = threadIdx.x;
    const int lane = tid & 31;
    const int wid  = tid >> 5;
    const int wm   = wid >> 2;          // 0..1
    const int wn   = wid & 3;           // 0..3
    const int n0 = blockIdx.x * 128;
    const int m0 = blockIdx.y * 128;
    const int NC = K >> 6;              // K/64 chunks (always 32 here)

    const int a_r  = (lane & 7) + ((lane >> 3) & 1) * 8;
    const int a_cb = ((lane >> 4) & 1) * 16;
    const int b_r  = (lane & 7) + ((lane >> 4) & 1) * 8;
    const int b_cb = ((lane >> 3) & 1) * 16;

    float acc[4][4][4];
#pragma unroll
    for (int i = 0; i < 4; i++)
#pragma unroll
        for (int j = 0; j < 4; j++)
#pragma unroll
            for (int r = 0; r < 4; r++) acc[i][j][r] = 0.f;

    auto load_stage = [&](int buf, int k0) {
        const __nv_bfloat16* srcs[4] = {Ahi, Alo, Bhi, Blo};
        const int r0s[4] = {m0, m0, n0, n0};
#pragma unroll
        for (int tm = 0; tm < 4; tm++) {
            uint32_t tb = sb + (uint32_t)buf * 65536u + (uint32_t)tm * 16384u;
#pragma unroll
            for (int i = 0; i < 4; i++) {
                int idx = tid + i * 256;
                int row = idx >> 3;
                int c   = idx & 7;
                const void* g = (const void*)(srcs[tm] + (size_t)(r0s[tm] + row) * K + k0 + c * 8);
                CP_ASYNC16(tb + swz(row, c * 16), g);
            }
        }
    };

    // prologue: fill 3 stages
    load_stage(0, 0);   CP_COMMIT();
    load_stage(1, 64);  CP_COMMIT();
    load_stage(2, 128); CP_COMMIT();

    int buf = 0;
    for (int it = 0; it < NC; it++) {
        CP_WAIT(2);
        __syncthreads();
        uint32_t stg = sb + (uint32_t)buf * 65536u;

#pragma unroll 1
        for (int kk = 0; kk < 4; kk++) {
            uint32_t ah[4][4], al[4][4], bh[2][4], bl[2][4];
#pragma unroll
            for (int mi = 0; mi < 4; mi++) {
                uint32_t off = swz(wm * 64 + mi * 16 + a_r, kk * 32 + a_cb);
                LDMX4(ah[mi][0], ah[mi][1], ah[mi][2], ah[mi][3], stg + off);
                LDMX4(al[mi][0], al[mi][1], al[mi][2], al[mi][3], stg + 16384u + off);
            }
#pragma unroll
            for (int bt = 0; bt < 2; bt++) {
                uint32_t off = swz(wn * 32 + bt * 16 + b_r, kk * 32 + b_cb);
                LDMX4(bh[bt][0], bh[bt][1], bh[bt][2], bh[bt][3], stg + 32768u + off);
                LDMX4(bl[bt][0], bl[bt][1], bl[bt][2], bl[bt][3], stg + 49152u + off);
            }
#pragma unroll
            for (int mi = 0; mi < 4; mi++)
#pragma unroll
                for (int ni = 0; ni < 4; ni++) {
                    int bt = ni >> 1, pr = (ni & 1) * 2;
                    MMA16816(acc[mi][ni], ah[mi], bh[bt][pr], bh[bt][pr + 1]);
                    MMA16816(acc[mi][ni], ah[mi], bl[bt][pr], bl[bt][pr + 1]);
                    MMA16816(acc[mi][ni], al[mi], bh[bt][pr], bh[bt][pr + 1]);
                }
        }
        __syncthreads();            // all warps done reading buf
        if (it + 3 < NC) load_stage(buf, (it + 3) * 64);
        CP_COMMIT();                // unconditional (empty groups at tail)
        buf = (buf == 2) ? 0 : buf + 1;
    }

    // ---- Epilogue ----
    const int gi = lane >> 2;
    const int ci = lane & 3;

    if (MODE == 2) {
        const bool isIF = (lane & 1) == 0;
        int rowm[4];
        float vv0[4], vv1[4];
#pragma unroll
        for (int mi = 0; mi < 4; mi++) {
            rowm[mi] = m0 + wm * 64 + mi * 16 + gi + (isIF ? 0 : 8);
            size_t vr = ((size_t)rowm[mi] * TT + t) * 2;
            vv0[mi] = v[vr];
            vv1[mi] = v[vr + 1];
        }
#pragma unroll
        for (int mi = 0; mi < 4; mi++)
#pragma unroll
            for (int ni = 0; ni < 4; ni++) {
                float c0 = acc[mi][ni][0], c1 = acc[mi][ni][1];
                float c2 = acc[mi][ni][2], c3 = acc[mi][ni][3];
                float o0 = __shfl_xor_sync(0xFFFFFFFFu, c0, 1);
                float o1 = __shfl_xor_sync(0xFFFFFFFFu, c1, 1);
                float o2 = __shfl_xor_sync(0xFFFFFFFFu, c2, 1);
                float o3 = __shfl_xor_sync(0xFFFFFFFFu, c3, 1);
                float zi = isIF ? c0 : o2;
                float zf = isIF ? c1 : o3;
                float zg = isIF ? o0 : c2;
                float zo = isIF ? o1 : c3;
                int row  = rowm[mi];
                int qcol = n0 + wn * 32 + ni * 8 + (ci >> 1) * 4;
                float4 q0 = *(const float4*)&d_W2pk[qcol];
                float4 q1 = *(const float4*)&d_W2pk[G4 + qcol];
                float4 qb = *(const float4*)&d_b2pk[qcol];
                zi += fmaf(vv0[mi], q0.x, fmaf(vv1[mi], q1.x, qb.x));
                zf += fmaf(vv0[mi], q0.y, fmaf(vv1[mi], q1.y, qb.y));
                zg += fmaf(vv0[mi], q0.z, fmaf(vv1[mi], q1.z, qb.z));
                zo += fmaf(vv0[mi], q0.w, fmaf(vv1[mi], q1.w, qb.w));
                float ig = sigmoidf_(zi);
                float fg = sigmoidf_(zf);
                float gg = fmaxf(zg, 0.f);
                float og = sigmoidf_(zo);
                int gcol = qcol >> 2;
                size_t cidx = (size_t)row * NG + gcol;
                float cn = fmaf(fg, c_state[cidx], ig * gg);
                c_state[cidx] = cn;
                float h = og * fmaxf(cn, 0.f);
                __nv_bfloat16 hh = __float2bfloat16(h);
                __nv_bfloat16 hl = __float2bfloat16(h - __bfloat162float(hh));
                o_hi[cidx] = hh;
                o_lo[cidx] = hl;
                size_t hsx = ((size_t)row * TT + t) * (size_t)NG + gcol;
                hs_hi[hsx] = hh;
                hs_lo[hsx] = hl;
            }
    } else {
#pragma unroll
        for (int mi = 0; mi < 4; mi++)
#pragma unroll
            for (int ni = 0; ni < 4; ni++) {
                int row0 = m0 + wm * 64 + mi * 16 + gi;
                int col  = n0 + wn * 32 + ni * 8 + ci * 2;
                float bx = bias[col], by = bias[col + 1];
                float r0 = acc[mi][ni][0] + bx, r1 = acc[mi][ni][1] + by;
                float r2 = acc[mi][ni][2] + bx, r3 = acc[mi][ni][3] + by;
                if (MODE == 0) {
                    *(float2*)(Cout + (size_t)row0 * N + col)       = make_float2(r0, r1);
                    *(float2*)(Cout + (size_t)(row0 + 8) * N + col) = make_float2(r2, r3);
                } else {
                    r0 = fmaxf(r0, 0.f); r1 = fmaxf(r1, 0.f);
                    r2 = fmaxf(r2, 0.f); r3 = fmaxf(r3, 0.f);
                    __nv_bfloat16 h0 = __float2bfloat16(r0), h1 = __float2bfloat16(r1);
                    __nv_bfloat16 h2 = __float2bfloat16(r2), h3 = __float2bfloat16(r3);
                    size_t i0 = (size_t)row0 * N + col;
                    size_t i1 = (size_t)(row0 + 8) * N + col;
                    *(__nv_bfloat162*)(o_hi + i0) = __nv_bfloat162(h0, h1);
                    *(__nv_bfloat162*)(o_hi + i1) = __nv_bfloat162(h2, h3);
                    *(__nv_bfloat162*)(o_lo + i0) = __nv_bfloat162(
                        __float2bfloat16(r0 - __bfloat162float(h0)),
                        __float2bfloat16(r1 - __bfloat162float(h1)));
                    *(__nv_bfloat162*)(o_lo + i1) = __nv_bfloat162(
                        __float2bfloat16(r2 - __bfloat162float(h2)),
                        __float2bfloat16(r3 - __bfloat162float(h3)));
                }
            }
    }
}

// ---------------------------------------------------------------------------
extern "C" void kernel_launch(void* const* d_in, const int* in_sizes, int n_in,
                              void* d_out, int out_size) {
    const float* v       = (const float*)d_in[0];
    const float* p0      = (const float*)d_in[1];
    const float* enc1_W  = (const float*)d_in[2];
    const float* enc1_b  = (const float*)d_in[3];
    const float* enc2_W  = (const float*)d_in[4];
    const float* enc2_b  = (const float*)d_in[5];
    const float* lstm_W  = (const float*)d_in[8];
    const float* lstm_U  = (const float*)d_in[9];
    const float* lstm_b  = (const float*)d_in[10];
    const float* M_W     = (const float*)d_in[6];
    const float* M_b     = (const float*)d_in[7];
    const float* dense_W = (const float*)d_in[11];
    const float* dense_b = (const float*)d_in[12];
    const float* dec_W   = (const float*)d_in[13];
    const float* dec_b   = (const float*)d_in[14];
    float* out = (float*)d_out;

    __nv_bfloat16 *Uhi, *Ulo, *DWhi, *DWlo, *DChi, *DClo;
    __nv_bfloat16 *hhi, *hlo, *hshi, *hslo, *ghi, *glo;
    float *cp;
    cudaGetSymbolAddress((void**)&Uhi,  d_Uhi);
    cudaGetSymbolAddress((void**)&Ulo,  d_Ulo);
    cudaGetSymbolAddress((void**)&DWhi, d_DWhi);
    cudaGetSymbolAddress((void**)&DWlo, d_DWlo);
    cudaGetSymbolAddress((void**)&DChi, d_DChi);
    cudaGetSymbolAddress((void**)&DClo, d_DClo);
    cudaGetSymbolAddress((void**)&hhi,  d_hhi);
    cudaGetSymbolAddress((void**)&hlo,  d_hlo);
    cudaGetSymbolAddress((void**)&hshi, d_hshi);
    cudaGetSymbolAddress((void**)&hslo, d_hslo);
    cudaGetSymbolAddress((void**)&ghi,  d_ghi);
    cudaGetSymbolAddress((void**)&glo,  d_glo);
    cudaGetSymbolAddress((void**)&cp,   d_cbuf);

    const int SMEMSZ = 3 * 65536;  // 192 KB, 3-stage pipeline
    cudaFuncSetAttribute(hmma_gemm<0>, cudaFuncAttributeMaxDynamicSharedMemorySize, SMEMSZ);
    cudaFuncSetAttribute(hmma_gemm<1>, cudaFuncAttributeMaxDynamicSharedMemorySize, SMEMSZ);
    cudaFuncSetAttribute(hmma_gemm<2>, cudaFuncAttributeMaxDynamicSharedMemorySize, SMEMSZ);

    // 1) Weight prep (2 launches)
    prep_w2_k<<<G4 / 256, 256>>>(lstm_W, lstm_b, M_W, M_b);
    transp_split_all<<<21504, dim3(32, 8)>>>(lstm_U, dense_W, dec_W);

    // 2) Initial state (1 launch, z-fused): h0 split bf16 + c0 fp32
    enc_k<<<dim3(NG / 64, BB / 128, 2), 256>>>(p0, enc1_W, enc1_b, enc2_W, enc2_b,
                                               hhi, hlo, cp);

    // 3) Recurrence: 100 HMMA steps with fused gate epilogue
    const size_t HP = (size_t)BB * NG;
    for (int tstep = 0; tstep < TT; tstep++) {
        int pi = tstep & 1, po = (tstep + 1) & 1;
        hmma_gemm<2><<<dim3(G4 / 128, BB / 128), 256, SMEMSZ>>>(
            hhi + pi * HP, hlo + pi * HP, Uhi, Ulo, nullptr, nullptr, G4, NG,
            v, cp, hhi + po * HP, hlo + po * HP, hshi, hslo, tstep);
    }

    // 4) dense: g = relu(hs @ dense_W + b) -> split bf16
    hmma_gemm<1><<<dim3(NG / 128, MTR / 128), 256, SMEMSZ>>>(
        hshi, hslo, DWhi, DWlo, dense_b, nullptr, NG, NG,
        nullptr, nullptr, ghi, glo, nullptr, nullptr, 0);

    // 5) dec: out = g @ dec_W + b -> fp32
    hmma_gemm<0><<<dim3(NP / 128, MTR / 128), 256, SMEMSZ>>>(
        ghi, glo, DChi, DClo, dec_b, out, NP, NG,
        nullptr, nullptr, nullptr, nullptr, nullptr, nullptr, 0);
}